// round 14
// baseline (speedup 1.0000x reference)
#include <cuda_runtime.h>
#include <cuda_fp16.h>
#include <cstdint>
#include <math.h>

#define Dh     1024
#define NH     16
#define HD     64
#define SEQ    2048
#define BATCH  4
#define MROWS  8192   // BATCH*SEQ

// ---------------- scratch (static device globals; no allocation) -------------
__device__ half  g_x16[(size_t)MROWS * Dh];                 // X fp16 [M,1024]
__device__ half  g_wq16[(size_t)Dh * Dh];
__device__ half  g_wk16[(size_t)Dh * Dh];
__device__ half  g_wv16[(size_t)Dh * Dh];
__device__ half  g_wo16[(size_t)Dh * Dh];
__device__ half  g_q16[(size_t)MROWS * Dh];  // [B,H,S,DH] (pre-scaled by 0.125)
__device__ half  g_k16[(size_t)MROWS * Dh];  // [B,H,S,DH]
__device__ half  g_v16[(size_t)MROWS * Dh];  // [B,H,DH,S]  (transposed)
__device__ half  g_cx16[(size_t)MROWS * Dh];                // ctx fp16 [M,1024]

// ======================= helpers =============================================
__device__ __forceinline__ uint32_t smem_u32(const void* p) {
    uint32_t a;
    asm("{ .reg .u64 t; cvta.to.shared.u64 t, %1; cvt.u32.u64 %0, t; }" : "=r"(a) : "l"(p));
    return a;
}
__device__ __forceinline__ void mma_f16(float d[4],
                                        uint32_t a0, uint32_t a1, uint32_t a2, uint32_t a3,
                                        uint32_t b0, uint32_t b1) {
    asm("mma.sync.aligned.m16n8k16.row.col.f32.f16.f16.f32 "
        "{%0,%1,%2,%3}, {%4,%5,%6,%7}, {%8,%9}, {%0,%1,%2,%3};"
        : "+f"(d[0]), "+f"(d[1]), "+f"(d[2]), "+f"(d[3])
        : "r"(a0), "r"(a1), "r"(a2), "r"(a3), "r"(b0), "r"(b1));
}
__device__ __forceinline__ void ldm_x4(uint32_t& r0, uint32_t& r1, uint32_t& r2,
                                       uint32_t& r3, uint32_t addr) {
    asm volatile("ldmatrix.sync.aligned.m8n8.x4.shared.b16 {%0,%1,%2,%3}, [%4];"
        : "=r"(r0), "=r"(r1), "=r"(r2), "=r"(r3) : "r"(addr));
}
#define CP_ASYNC16(dst_u32, src_ptr) \
    asm volatile("cp.async.ca.shared.global [%0], [%1], 16;" :: "r"(dst_u32), "l"(src_ptr))
#define CP_COMMIT() asm volatile("cp.async.commit_group;" ::: "memory")
#define CP_WAIT(n)  asm volatile("cp.async.wait_group %0;" :: "n"(n) : "memory")

// ================== fp32 -> fp16 convert =====================================
__global__ __launch_bounds__(256) void cvt16(const float* __restrict__ in,
                                             half* __restrict__ out, int n4)
{
    int i = blockIdx.x * 256 + threadIdx.x;
    if (i >= n4) return;
    float4 v = ((const float4*)in)[i];
    __half2 a = __floats2half2_rn(v.x, v.y);
    __half2 b = __floats2half2_rn(v.z, v.w);
    *(uint2*)&out[(size_t)i * 4] = make_uint2(*(uint32_t*)&a, *(uint32_t*)&b);
}

// all four weight matrices in one launch (blockIdx.y selects)
__global__ __launch_bounds__(256) void cvtW(
    const float* __restrict__ W0, const float* __restrict__ W1,
    const float* __restrict__ W2, const float* __restrict__ W3,
    half* __restrict__ o0, half* __restrict__ o1,
    half* __restrict__ o2, half* __restrict__ o3, int n4)
{
    int i = blockIdx.x * 256 + threadIdx.x;
    if (i >= n4) return;
    const float* in = (blockIdx.y == 0) ? W0 : (blockIdx.y == 1) ? W1
                     : (blockIdx.y == 2) ? W2 : W3;
    half* out = (blockIdx.y == 0) ? o0 : (blockIdx.y == 1) ? o1
               : (blockIdx.y == 2) ? o2 : o3;
    float4 v = ((const float4*)in)[i];
    __half2 a = __floats2half2_rn(v.x, v.y);
    __half2 b = __floats2half2_rn(v.z, v.w);
    *(uint2*)&out[(size_t)i * 4] = make_uint2(*(uint32_t*)&a, *(uint32_t*)&b);
}

// ============== fp16 x1 mma.sync GEMM core (3-stage, 1 sync/chunk) ===========
#define AS        40                       // smem row stride in fp16 (32 + 8 pad)
#define A_STG     (256 * AS)               // 10240 fp16
#define W_STG     (128 * AS)               // 5120 fp16
#define SPAN      (A_STG + W_STG)          // 15360 fp16
#define NSTG      3
#define GEMM_SMEM (NSTG * SPAN * 2)        // 92160 bytes
#define NC        (Dh / 32)                // 32 chunks

// modes: 0 fp32 flat; 1 fp16 head; 2 fp16 transposed; 3 fp16 head scaled 0.125
__device__ __forceinline__ void gemm_core(
    const half* __restrict__ A, const half* __restrict__ W,
    const float* __restrict__ bias, float* __restrict__ outF,
    half* __restrict__ outX, int mode, int m0, int n0, half* sb)
{
    const int tid   = threadIdx.x;
    const int lane  = tid & 31;
    const int wid   = tid >> 5;
    const int warpM = wid >> 1;
    const int warpN = wid & 1;
    const int gid = lane >> 2;
    const int tig = lane & 3;

    const int aRow = (lane & 7) + ((lane >> 3) & 1) * 8;
    const int aCol = (lane >> 4) * 8;
    const int bRow = (lane & 7) + (lane >> 4) * 8;
    const int bCol = ((lane >> 3) & 1) * 8;

    float d[2][8][4];
#pragma unroll
    for (int mt = 0; mt < 2; ++mt)
#pragma unroll
        for (int nt = 0; nt < 8; ++nt)
#pragma unroll
            for (int q = 0; q < 4; ++q) d[mt][nt][q] = 0.f;

    const uint32_t sbu = smem_u32(sb);

#define ISSUE(c) do {                                                              \
    const int stg = (c) % NSTG;                                                    \
    const uint32_t ob = sbu + (uint32_t)stg * SPAN * 2;                            \
    const half* sA = A + (size_t)m0 * Dh + (c) * 32;                               \
    const half* sW = W + (size_t)n0 * Dh + (c) * 32;                               \
    _Pragma("unroll")                                                              \
    for (int rep = 0; rep < 2; ++rep) {                                            \
        int idx = rep * 512 + tid;                                                 \
        int r = idx >> 2, c8 = (idx & 3) * 8;                                      \
        CP_ASYNC16(ob + (uint32_t)(r * AS + c8) * 2, sA + (size_t)r * Dh + c8);    \
    }                                                                              \
    {                                                                              \
        int r = tid >> 2, c8 = (tid & 3) * 8;                                      \
        CP_ASYNC16(ob + A_STG * 2 + (uint32_t)(r * AS + c8) * 2,                   \
                   sW + (size_t)r * Dh + c8);                                      \
    }                                                                              \
    CP_COMMIT();                                                                   \
} while (0)

    ISSUE(0);
    ISSUE(1);

    for (int c = 0; c < NC; ++c) {
        if (c + 1 < NC) CP_WAIT(1);
        else            CP_WAIT(0);
        __syncthreads();
        if (c + 2 < NC) ISSUE(c + 2);

        const uint32_t base = sbu + (uint32_t)(c % NSTG) * SPAN * 2;
        const uint32_t aB = base;
        const uint32_t wB = base + A_STG * 2;

#pragma unroll
        for (int kk = 0; kk < 2; ++kk) {
            const int kb = kk * 16;

            uint32_t af[2][4];
#pragma unroll
            for (int mt = 0; mt < 2; ++mt) {
                const uint32_t off = (uint32_t)((warpM * 32 + mt * 16 + aRow) * AS + kb + aCol) * 2;
                ldm_x4(af[mt][0], af[mt][1], af[mt][2], af[mt][3], aB + off);
            }
#pragma unroll
            for (int P = 0; P < 4; ++P) {
                const uint32_t off = (uint32_t)((warpN * 64 + P * 16 + bRow) * AS + kb + bCol) * 2;
                uint32_t w0, w1, w2, w3;
                ldm_x4(w0, w1, w2, w3, wB + off);
                mma_f16(d[0][2*P],   af[0][0], af[0][1], af[0][2], af[0][3], w0, w1);
                mma_f16(d[1][2*P],   af[1][0], af[1][1], af[1][2], af[1][3], w0, w1);
                mma_f16(d[0][2*P+1], af[0][0], af[0][1], af[0][2], af[0][3], w2, w3);
                mma_f16(d[1][2*P+1], af[1][0], af[1][1], af[1][2], af[1][3], w2, w3);
            }
        }
    }
#undef ISSUE

    const float scl = (mode == 3) ? 0.125f : 1.f;
#pragma unroll
    for (int mt = 0; mt < 2; ++mt) {
        const int mrow = m0 + warpM * 32 + mt * 16 + gid;
#pragma unroll
        for (int nt = 0; nt < 8; ++nt) {
            const int ncol = n0 + warpN * 64 + nt * 8 + tig * 2;
            const float b0 = bias[ncol], b1 = bias[ncol + 1];
            if (mode == 0) {
                *(float2*)&outF[(size_t)mrow * Dh + ncol] =
                    make_float2(d[mt][nt][0] + b0, d[mt][nt][1] + b1);
                *(float2*)&outF[(size_t)(mrow + 8) * Dh + ncol] =
                    make_float2(d[mt][nt][2] + b0, d[mt][nt][3] + b1);
            } else if (mode == 2) {
                const int h = ncol >> 6, dh0 = ncol & 63;
#pragma unroll
                for (int rr = 0; rr < 2; ++rr) {
                    const int m = mrow + rr * 8;
                    const int bb = m >> 11, s = m & 2047;
                    size_t base = ((size_t)(bb * NH + h) * HD) * SEQ + s;
                    outX[base + (size_t)dh0 * SEQ]       = __float2half_rn(d[mt][nt][rr * 2 + 0] + b0);
                    outX[base + (size_t)(dh0 + 1) * SEQ] = __float2half_rn(d[mt][nt][rr * 2 + 1] + b1);
                }
            } else {
                const int h = ncol >> 6, dh0 = ncol & 63;
#pragma unroll
                for (int rr = 0; rr < 2; ++rr) {
                    const int m = mrow + rr * 8;
                    const int bb = m >> 11, s = m & 2047;
                    __half2 pk = __floats2half2_rn((d[mt][nt][rr * 2 + 0] + b0) * scl,
                                                   (d[mt][nt][rr * 2 + 1] + b1) * scl);
                    *(uint32_t*)&outX[((size_t)(bb * NH + h) * SEQ + s) * HD + dh0] = *(uint32_t*)&pk;
                }
            }
        }
    }
}

// fused Q/K/V projection: blockIdx.z selects weight/output/mode
__global__ __launch_bounds__(512, 1) void gemm_qkv(
    const half* __restrict__ A,
    const half* __restrict__ Wq, const half* __restrict__ Wk, const half* __restrict__ Wv,
    const float* __restrict__ bq, const float* __restrict__ bk, const float* __restrict__ bv,
    half* __restrict__ q16, half* __restrict__ k16, half* __restrict__ v16)
{
    extern __shared__ half sb[];
    const int z = blockIdx.z;
    const half*  W    = (z == 0) ? Wq : (z == 1) ? Wk : Wv;
    const float* bias = (z == 0) ? bq : (z == 1) ? bk : bv;
    half*        outX = (z == 0) ? q16 : (z == 1) ? k16 : v16;
    const int mode    = (z == 0) ? 3 : (z == 1) ? 1 : 2;
    gemm_core(A, W, bias, nullptr, outX, mode, blockIdx.y * 256, blockIdx.x * 128, sb);
}

// output projection (fp32 out)
__global__ __launch_bounds__(512, 1) void gemm_out(
    const half* __restrict__ A, const half* __restrict__ W,
    const float* __restrict__ bias, float* __restrict__ outF)
{
    extern __shared__ half sb[];
    gemm_core(A, W, bias, outF, nullptr, 0, blockIdx.y * 256, blockIdx.x * 128, sb);
}

// ==== fp16 x1 flash attention (mma.sync + ldmatrix + 3-stage cp.async) =======
#define AT_STRIDE 72                        // smem row stride in fp16 (64 + 8 pad)
#define AT_MAT    (64 * AT_STRIDE)          // one 64x64 matrix (fp16 units)
#define ATT_SPAN  (2 * AT_MAT)              // K, V per stage
#define ATT_NSTG  3
#define ATT_SMEM  (ATT_NSTG * ATT_SPAN * 2) // 55296 bytes
#define NT        (SEQ / 64)                // 32 KV tiles

__global__ __launch_bounds__(256, 2) void attn_mma(
    const half* __restrict__ Q, const half* __restrict__ K,
    const half* __restrict__ V, half* __restrict__ ctx16)
{
    extern __shared__ half asm_[];

    const int tid  = threadIdx.x;
    const int lane = tid & 31;
    const int wid  = tid >> 5;
    const int gid  = lane >> 2;
    const int tig  = lane & 3;
    const int bh   = blockIdx.y;
    const int q0   = blockIdx.x * 128;
    const int wq   = q0 + wid * 16;

    const int bRow = (lane & 7) + (lane >> 4) * 8;
    const int bCol = ((lane >> 3) & 1) * 8;
    const uint32_t smu = smem_u32(asm_);

    const half* bK = K + (size_t)bh * SEQ * HD;
    const half* bV = V + (size_t)bh * SEQ * HD;   // [DH][SEQ]

#define ISSUEA(t) do {                                                             \
    const int stg = (t) % ATT_NSTG;                                                \
    const uint32_t ob = smu + (uint32_t)stg * ATT_SPAN * 2;                        \
    const half* pK = bK + (size_t)(t) * 64 * HD;                                   \
    _Pragma("unroll")                                                              \
    for (int rep = 0; rep < 2; ++rep) {                                            \
        int idx = rep * 256 + tid;          /* 0..511 */                           \
        int row = idx >> 3, col8 = (idx & 7) * 8;                                  \
        uint32_t doff = (uint32_t)(row * AT_STRIDE + col8) * 2;                    \
        CP_ASYNC16(ob + doff,              pK + (size_t)row * HD + col8);          \
        CP_ASYNC16(ob + AT_MAT * 2 + doff, bV + (size_t)row * SEQ + (t) * 64 + col8); \
    }                                                                              \
    CP_COMMIT();                                                                   \
} while (0)

    uint32_t qf[4][4];
    {
        const half* bq = Q + ((size_t)bh * SEQ + wq) * HD;
#pragma unroll
        for (int j = 0; j < 4; ++j) {
            int e0 = 16 * j + 2 * tig;
            qf[j][0] = *(const uint32_t*)(bq + (size_t)gid * HD + e0);
            qf[j][1] = *(const uint32_t*)(bq + (size_t)(gid + 8) * HD + e0);
            qf[j][2] = *(const uint32_t*)(bq + (size_t)gid * HD + e0 + 8);
            qf[j][3] = *(const uint32_t*)(bq + (size_t)(gid + 8) * HD + e0 + 8);
        }
    }

    float cx[8][4];
#pragma unroll
    for (int nt = 0; nt < 8; ++nt)
#pragma unroll
        for (int q = 0; q < 4; ++q) cx[nt][q] = 0.f;
    float m0 = -1e30f, m1 = -1e30f, l0 = 0.f, l1 = 0.f;

    ISSUEA(0);
    ISSUEA(1);

    for (int kt = 0; kt < NT; ++kt) {
        if (kt + 1 < NT) CP_WAIT(1);
        else             CP_WAIT(0);
        __syncthreads();
        if (kt + 2 < NT) ISSUEA(kt + 2);

        const uint32_t sbase = smu + (uint32_t)(kt % ATT_NSTG) * ATT_SPAN * 2;
        const uint32_t uK = sbase;
        const uint32_t uV = sbase + AT_MAT * 2;

        float sacc[8][4];
#pragma unroll
        for (int nt = 0; nt < 8; ++nt)
#pragma unroll
            for (int q = 0; q < 4; ++q) sacc[nt][q] = 0.f;

#pragma unroll
        for (int j = 0; j < 4; ++j) {
            const uint32_t coff = (uint32_t)(16 * j + bCol) * 2;
#pragma unroll
            for (int P = 0; P < 4; ++P) {
                const uint32_t off = (uint32_t)((P * 16 + bRow) * AT_STRIDE) * 2 + coff;
                uint32_t k0, k1, k2, k3;
                ldm_x4(k0, k1, k2, k3, uK + off);
                mma_f16(sacc[2*P],   qf[j][0], qf[j][1], qf[j][2], qf[j][3], k0, k1);
                mma_f16(sacc[2*P+1], qf[j][0], qf[j][1], qf[j][2], qf[j][3], k2, k3);
            }
        }

        float mx0 = -1e30f, mx1 = -1e30f;
#pragma unroll
        for (int nt = 0; nt < 8; ++nt) {
            mx0 = fmaxf(mx0, fmaxf(sacc[nt][0], sacc[nt][1]));
            mx1 = fmaxf(mx1, fmaxf(sacc[nt][2], sacc[nt][3]));
        }
        mx0 = fmaxf(mx0, __shfl_xor_sync(0xffffffffu, mx0, 1));
        mx0 = fmaxf(mx0, __shfl_xor_sync(0xffffffffu, mx0, 2));
        mx1 = fmaxf(mx1, __shfl_xor_sync(0xffffffffu, mx1, 1));
        mx1 = fmaxf(mx1, __shfl_xor_sync(0xffffffffu, mx1, 2));
        float mn0 = fmaxf(m0, mx0), mn1 = fmaxf(m1, mx1);
        float r0 = __expf(m0 - mn0), r1 = __expf(m1 - mn1);
        m0 = mn0; m1 = mn1;

        float s0 = 0.f, s1 = 0.f;
#pragma unroll
        for (int nt = 0; nt < 8; ++nt) {
            float e0 = __expf(sacc[nt][0] - mn0);
            float e1 = __expf(sacc[nt][1] - mn0);
            float e2 = __expf(sacc[nt][2] - mn1);
            float e3 = __expf(sacc[nt][3] - mn1);
            sacc[nt][0] = e0; sacc[nt][1] = e1; sacc[nt][2] = e2; sacc[nt][3] = e3;
            s0 += e0 + e1; s1 += e2 + e3;
        }
        s0 += __shfl_xor_sync(0xffffffffu, s0, 1);
        s0 += __shfl_xor_sync(0xffffffffu, s0, 2);
        s1 += __shfl_xor_sync(0xffffffffu, s1, 1);
        s1 += __shfl_xor_sync(0xffffffffu, s1, 2);
        l0 = l0 * r0 + s0; l1 = l1 * r1 + s1;

#pragma unroll
        for (int nt = 0; nt < 8; ++nt) {
            cx[nt][0] *= r0; cx[nt][1] *= r0;
            cx[nt][2] *= r1; cx[nt][3] *= r1;
        }

#pragma unroll
        for (int j = 0; j < 4; ++j) {
            uint32_t pa[4];
            __half2 t0 = __floats2half2_rn(sacc[2*j][0],   sacc[2*j][1]);
            __half2 t1 = __floats2half2_rn(sacc[2*j][2],   sacc[2*j][3]);
            __half2 t2 = __floats2half2_rn(sacc[2*j+1][0], sacc[2*j+1][1]);
            __half2 t3 = __floats2half2_rn(sacc[2*j+1][2], sacc[2*j+1][3]);
            pa[0] = *(uint32_t*)&t0; pa[1] = *(uint32_t*)&t1;
            pa[2] = *(uint32_t*)&t2; pa[3] = *(uint32_t*)&t3;
            const uint32_t coff = (uint32_t)(16 * j + bCol) * 2;
#pragma unroll
            for (int P = 0; P < 4; ++P) {
                const uint32_t off = (uint32_t)((P * 16 + bRow) * AT_STRIDE) * 2 + coff;
                uint32_t v0, v1, v2, v3;
                ldm_x4(v0, v1, v2, v3, uV + off);
                mma_f16(cx[2*P],   pa[0], pa[1], pa[2], pa[3], v0, v1);
                mma_f16(cx[2*P+1], pa[0], pa[1], pa[2], pa[3], v2, v3);
            }
        }
    }
#undef ISSUEA

    // ---- epilogue: ctx fp16 single, flat [M,1024] ----
    const int b = bh >> 4, h = bh & 15;
    const float inv0 = 1.f / l0, inv1 = 1.f / l1;
    const int row0 = wq + gid, row1 = wq + gid + 8;
#pragma unroll
    for (int nt = 0; nt < 8; ++nt) {
        const int dcol = h * HD + 8 * nt + 2 * tig;
        __half2 p0 = __floats2half2_rn(cx[nt][0] * inv0, cx[nt][1] * inv0);
        __half2 p1 = __floats2half2_rn(cx[nt][2] * inv1, cx[nt][3] * inv1);
        *(uint32_t*)&ctx16[(size_t)(b * SEQ + row0) * Dh + dcol] = *(uint32_t*)&p0;
        *(uint32_t*)&ctx16[(size_t)(b * SEQ + row1) * Dh + dcol] = *(uint32_t*)&p1;
    }
}

// ---------------- launch ------------------------------------------------------
extern "C" void kernel_launch(void* const* d_in, const int* in_sizes, int n_in,
                              void* d_out, int out_size)
{
    const float* X  = (const float*)d_in[0];
    const float* Wq = (const float*)d_in[1];
    const float* bq = (const float*)d_in[2];
    const float* Wk = (const float*)d_in[3];
    const float* bk = (const float*)d_in[4];
    const float* Wv = (const float*)d_in[5];
    const float* bv = (const float*)d_in[6];
    const float* Wo = (const float*)d_in[7];
    const float* bo = (const float*)d_in[8];
    float* out = (float*)d_out;

    half *x16, *wq16, *wk16, *wv16, *wo16, *q16, *k16, *v16, *cx16;
    cudaGetSymbolAddress((void**)&x16,  g_x16);
    cudaGetSymbolAddress((void**)&wq16, g_wq16);
    cudaGetSymbolAddress((void**)&wk16, g_wk16);
    cudaGetSymbolAddress((void**)&wv16, g_wv16);
    cudaGetSymbolAddress((void**)&wo16, g_wo16);
    cudaGetSymbolAddress((void**)&q16,  g_q16);
    cudaGetSymbolAddress((void**)&k16,  g_k16);
    cudaGetSymbolAddress((void**)&v16,  g_v16);
    cudaGetSymbolAddress((void**)&cx16, g_cx16);

    cudaFuncSetAttribute(gemm_qkv, cudaFuncAttributeMaxDynamicSharedMemorySize, GEMM_SMEM);
    cudaFuncSetAttribute(gemm_out, cudaFuncAttributeMaxDynamicSharedMemorySize, GEMM_SMEM);
    cudaFuncSetAttribute(attn_mma, cudaFuncAttributeMaxDynamicSharedMemorySize, ATT_SMEM);

    dim3 thr(256);
    cvt16<<<(MROWS * Dh / 4 + 255) / 256, thr>>>(X, x16, MROWS * Dh / 4);
    {
        dim3 gw((Dh * Dh / 4 + 255) / 256, 4);
        cvtW<<<gw, thr>>>(Wq, Wk, Wv, Wo, wq16, wk16, wv16, wo16, Dh * Dh / 4);
    }

    dim3 gthr(512);
    dim3 gq(Dh / 128, MROWS / 256, 3);  // (8, 32, 3)
    gemm_qkv<<<gq, gthr, GEMM_SMEM>>>(x16, wq16, wk16, wv16, bq, bk, bv, q16, k16, v16);

    dim3 ga(SEQ / 128, BATCH * NH);     // (16, 64)
    attn_mma<<<ga, thr, ATT_SMEM>>>(q16, k16, v16, cx16);

    dim3 gg(Dh / 128, MROWS / 256);     // (8, 32)
    gemm_out<<<gg, gthr, GEMM_SMEM>>>(cx16, wo16, bo, out);
}

// round 15
// speedup vs baseline: 1.5532x; 1.5532x over previous
#include <cuda_runtime.h>
#include <cuda_fp16.h>
#include <cstdint>
#include <math.h>

#define Dh     1024
#define NH     16
#define HD     64
#define SEQ    2048
#define BATCH  4
#define MROWS  8192   // BATCH*SEQ

// ---------------- scratch (static device globals; no allocation) -------------
__device__ half  g_x16[(size_t)MROWS * Dh];                 // X fp16 [M,1024]
__device__ half  g_wq16[(size_t)Dh * Dh];
__device__ half  g_wk16[(size_t)Dh * Dh];
__device__ half  g_wv16[(size_t)Dh * Dh];
__device__ half  g_wo16[(size_t)Dh * Dh];
__device__ half  g_q16[(size_t)MROWS * Dh];  // [B,H,S,DH] (pre-scaled by 0.125)
__device__ half  g_k16[(size_t)MROWS * Dh];  // [B,H,S,DH]
__device__ half  g_v16[(size_t)MROWS * Dh];  // [B,H,DH,S]  (transposed)
__device__ half  g_cx16[(size_t)MROWS * Dh];                // ctx fp16 [M,1024]

// ======================= helpers =============================================
__device__ __forceinline__ uint32_t smem_u32(const void* p) {
    uint32_t a;
    asm("{ .reg .u64 t; cvta.to.shared.u64 t, %1; cvt.u32.u64 %0, t; }" : "=r"(a) : "l"(p));
    return a;
}
__device__ __forceinline__ void mma_f16(float d[4],
                                        uint32_t a0, uint32_t a1, uint32_t a2, uint32_t a3,
                                        uint32_t b0, uint32_t b1) {
    asm("mma.sync.aligned.m16n8k16.row.col.f32.f16.f16.f32 "
        "{%0,%1,%2,%3}, {%4,%5,%6,%7}, {%8,%9}, {%0,%1,%2,%3};"
        : "+f"(d[0]), "+f"(d[1]), "+f"(d[2]), "+f"(d[3])
        : "r"(a0), "r"(a1), "r"(a2), "r"(a3), "r"(b0), "r"(b1));
}
__device__ __forceinline__ void ldm_x4(uint32_t& r0, uint32_t& r1, uint32_t& r2,
                                       uint32_t& r3, uint32_t addr) {
    asm volatile("ldmatrix.sync.aligned.m8n8.x4.shared.b16 {%0,%1,%2,%3}, [%4];"
        : "=r"(r0), "=r"(r1), "=r"(r2), "=r"(r3) : "r"(addr));
}
#define CP_ASYNC16(dst_u32, src_ptr) \
    asm volatile("cp.async.ca.shared.global [%0], [%1], 16;" :: "r"(dst_u32), "l"(src_ptr))
#define CP_COMMIT() asm volatile("cp.async.commit_group;" ::: "memory")
#define CP_WAIT(n)  asm volatile("cp.async.wait_group %0;" :: "n"(n) : "memory")

// ================== fp32 -> fp16 convert =====================================
__global__ __launch_bounds__(256) void cvt16(const float* __restrict__ in,
                                             half* __restrict__ out, int n4)
{
    int i = blockIdx.x * 256 + threadIdx.x;
    if (i >= n4) return;
    float4 v = ((const float4*)in)[i];
    __half2 a = __floats2half2_rn(v.x, v.y);
    __half2 b = __floats2half2_rn(v.z, v.w);
    *(uint2*)&out[(size_t)i * 4] = make_uint2(*(uint32_t*)&a, *(uint32_t*)&b);
}

// all four weight matrices in one launch (blockIdx.y selects)
__global__ __launch_bounds__(256) void cvtW(
    const float* __restrict__ W0, const float* __restrict__ W1,
    const float* __restrict__ W2, const float* __restrict__ W3,
    half* __restrict__ o0, half* __restrict__ o1,
    half* __restrict__ o2, half* __restrict__ o3, int n4)
{
    int i = blockIdx.x * 256 + threadIdx.x;
    if (i >= n4) return;
    const float* in = (blockIdx.y == 0) ? W0 : (blockIdx.y == 1) ? W1
                     : (blockIdx.y == 2) ? W2 : W3;
    half* out = (blockIdx.y == 0) ? o0 : (blockIdx.y == 1) ? o1
               : (blockIdx.y == 2) ? o2 : o3;
    float4 v = ((const float4*)in)[i];
    __half2 a = __floats2half2_rn(v.x, v.y);
    __half2 b = __floats2half2_rn(v.z, v.w);
    *(uint2*)&out[(size_t)i * 4] = make_uint2(*(uint32_t*)&a, *(uint32_t*)&b);
}

// ====== fp16 x1 mma.sync GEMM core (2-stage, ISSUE-before-WAIT, 2 syncs) =====
#define AS        40                       // smem row stride in fp16 (32 + 8 pad)
#define A_STG     (256 * AS)               // 10240 fp16
#define W_STG     (128 * AS)               // 5120 fp16
#define SPAN      (A_STG + W_STG)          // 15360 fp16
#define GEMM_SMEM (2 * SPAN * 2)           // 61440 bytes
#define NC        (Dh / 32)                // 32 chunks

// modes: 0 fp32 flat; 1 fp16 head; 2 fp16 transposed; 3 fp16 head scaled 0.125
__device__ __forceinline__ void gemm_core(
    const half* __restrict__ A, const half* __restrict__ W,
    const float* __restrict__ bias, float* __restrict__ outF,
    half* __restrict__ outX, int mode, int m0, int n0, half* sb)
{
    const int tid   = threadIdx.x;
    const int lane  = tid & 31;
    const int wid   = tid >> 5;
    const int warpM = wid >> 1;
    const int warpN = wid & 1;
    const int gid = lane >> 2;
    const int tig = lane & 3;

    const int aRow = (lane & 7) + ((lane >> 3) & 1) * 8;
    const int aCol = (lane >> 4) * 8;
    const int bRow = (lane & 7) + (lane >> 4) * 8;
    const int bCol = ((lane >> 3) & 1) * 8;

    float d[2][8][4];
#pragma unroll
    for (int mt = 0; mt < 2; ++mt)
#pragma unroll
        for (int nt = 0; nt < 8; ++nt)
#pragma unroll
            for (int q = 0; q < 4; ++q) d[mt][nt][q] = 0.f;

    const uint32_t sbu = smem_u32(sb);

#define ISSUE(c) do {                                                              \
    const int stg = (c) & 1;                                                       \
    const uint32_t ob = sbu + (uint32_t)stg * SPAN * 2;                            \
    const half* sA = A + (size_t)m0 * Dh + (c) * 32;                               \
    const half* sW = W + (size_t)n0 * Dh + (c) * 32;                               \
    _Pragma("unroll")                                                              \
    for (int rep = 0; rep < 2; ++rep) {                                            \
        int idx = rep * 512 + tid;                                                 \
        int r = idx >> 2, c8 = (idx & 3) * 8;                                      \
        CP_ASYNC16(ob + (uint32_t)(r * AS + c8) * 2, sA + (size_t)r * Dh + c8);    \
    }                                                                              \
    {                                                                              \
        int r = tid >> 2, c8 = (tid & 3) * 8;                                      \
        CP_ASYNC16(ob + A_STG * 2 + (uint32_t)(r * AS + c8) * 2,                   \
                   sW + (size_t)r * Dh + c8);                                      \
    }                                                                              \
    CP_COMMIT();                                                                   \
} while (0)

    ISSUE(0);

    for (int c = 0; c < NC; ++c) {
        if (c + 1 < NC) { ISSUE(c + 1); CP_WAIT(1); }
        else            { CP_WAIT(0); }
        __syncthreads();

        const uint32_t base = sbu + (uint32_t)(c & 1) * SPAN * 2;
        const uint32_t aB = base;
        const uint32_t wB = base + A_STG * 2;

#pragma unroll
        for (int kk = 0; kk < 2; ++kk) {
            const int kb = kk * 16;

            uint32_t af[2][4];
#pragma unroll
            for (int mt = 0; mt < 2; ++mt) {
                const uint32_t off = (uint32_t)((warpM * 32 + mt * 16 + aRow) * AS + kb + aCol) * 2;
                ldm_x4(af[mt][0], af[mt][1], af[mt][2], af[mt][3], aB + off);
            }
#pragma unroll
            for (int P = 0; P < 4; ++P) {
                const uint32_t off = (uint32_t)((warpN * 64 + P * 16 + bRow) * AS + kb + bCol) * 2;
                uint32_t w0, w1, w2, w3;
                ldm_x4(w0, w1, w2, w3, wB + off);
                mma_f16(d[0][2*P],   af[0][0], af[0][1], af[0][2], af[0][3], w0, w1);
                mma_f16(d[1][2*P],   af[1][0], af[1][1], af[1][2], af[1][3], w0, w1);
                mma_f16(d[0][2*P+1], af[0][0], af[0][1], af[0][2], af[0][3], w2, w3);
                mma_f16(d[1][2*P+1], af[1][0], af[1][1], af[1][2], af[1][3], w2, w3);
            }
        }
        __syncthreads();
    }
#undef ISSUE

    const float scl = (mode == 3) ? 0.125f : 1.f;
#pragma unroll
    for (int mt = 0; mt < 2; ++mt) {
        const int mrow = m0 + warpM * 32 + mt * 16 + gid;
#pragma unroll
        for (int nt = 0; nt < 8; ++nt) {
            const int ncol = n0 + warpN * 64 + nt * 8 + tig * 2;
            const float b0 = bias[ncol], b1 = bias[ncol + 1];
            if (mode == 0) {
                *(float2*)&outF[(size_t)mrow * Dh + ncol] =
                    make_float2(d[mt][nt][0] + b0, d[mt][nt][1] + b1);
                *(float2*)&outF[(size_t)(mrow + 8) * Dh + ncol] =
                    make_float2(d[mt][nt][2] + b0, d[mt][nt][3] + b1);
            } else if (mode == 2) {
                const int h = ncol >> 6, dh0 = ncol & 63;
#pragma unroll
                for (int rr = 0; rr < 2; ++rr) {
                    const int m = mrow + rr * 8;
                    const int bb = m >> 11, s = m & 2047;
                    size_t base = ((size_t)(bb * NH + h) * HD) * SEQ + s;
                    outX[base + (size_t)dh0 * SEQ]       = __float2half_rn(d[mt][nt][rr * 2 + 0] + b0);
                    outX[base + (size_t)(dh0 + 1) * SEQ] = __float2half_rn(d[mt][nt][rr * 2 + 1] + b1);
                }
            } else {
                const int h = ncol >> 6, dh0 = ncol & 63;
#pragma unroll
                for (int rr = 0; rr < 2; ++rr) {
                    const int m = mrow + rr * 8;
                    const int bb = m >> 11, s = m & 2047;
                    __half2 pk = __floats2half2_rn((d[mt][nt][rr * 2 + 0] + b0) * scl,
                                                   (d[mt][nt][rr * 2 + 1] + b1) * scl);
                    *(uint32_t*)&outX[((size_t)(bb * NH + h) * SEQ + s) * HD + dh0] = *(uint32_t*)&pk;
                }
            }
        }
    }
}

// fused Q/K/V projection: blockIdx.z selects weight/output/mode
__global__ __launch_bounds__(512, 1) void gemm_qkv(
    const half* __restrict__ A,
    const half* __restrict__ Wq, const half* __restrict__ Wk, const half* __restrict__ Wv,
    const float* __restrict__ bq, const float* __restrict__ bk, const float* __restrict__ bv,
    half* __restrict__ q16, half* __restrict__ k16, half* __restrict__ v16)
{
    extern __shared__ half sb[];
    const int z = blockIdx.z;
    const half*  W    = (z == 0) ? Wq : (z == 1) ? Wk : Wv;
    const float* bias = (z == 0) ? bq : (z == 1) ? bk : bv;
    half*        outX = (z == 0) ? q16 : (z == 1) ? k16 : v16;
    const int mode    = (z == 0) ? 3 : (z == 1) ? 1 : 2;
    gemm_core(A, W, bias, nullptr, outX, mode, blockIdx.y * 256, blockIdx.x * 128, sb);
}

// output projection (fp32 out)
__global__ __launch_bounds__(512, 1) void gemm_out(
    const half* __restrict__ A, const half* __restrict__ W,
    const float* __restrict__ bias, float* __restrict__ outF)
{
    extern __shared__ half sb[];
    gemm_core(A, W, bias, outF, nullptr, 0, blockIdx.y * 256, blockIdx.x * 128, sb);
}

// ==== fp16 x1 flash attention (2-stage, ISSUE-before-WAIT, 2 syncs) ==========
#define AT_STRIDE 72                        // smem row stride in fp16 (64 + 8 pad)
#define AT_MAT    (64 * AT_STRIDE)          // one 64x64 matrix (fp16 units)
#define ATT_SPAN  (2 * AT_MAT)              // K, V per stage
#define ATT_SMEM  (2 * ATT_SPAN * 2)        // 36864 bytes
#define NT        (SEQ / 64)                // 32 KV tiles

__global__ __launch_bounds__(256, 2) void attn_mma(
    const half* __restrict__ Q, const half* __restrict__ K,
    const half* __restrict__ V, half* __restrict__ ctx16)
{
    extern __shared__ half asm_[];

    const int tid  = threadIdx.x;
    const int lane = tid & 31;
    const int wid  = tid >> 5;
    const int gid  = lane >> 2;
    const int tig  = lane & 3;
    const int bh   = blockIdx.y;
    const int q0   = blockIdx.x * 128;
    const int wq   = q0 + wid * 16;

    const int bRow = (lane & 7) + (lane >> 4) * 8;
    const int bCol = ((lane >> 3) & 1) * 8;
    const uint32_t smu = smem_u32(asm_);

    const half* bK = K + (size_t)bh * SEQ * HD;
    const half* bV = V + (size_t)bh * SEQ * HD;   // [DH][SEQ]

#define ISSUEA(t) do {                                                             \
    const int stg = (t) & 1;                                                       \
    const uint32_t ob = smu + (uint32_t)stg * ATT_SPAN * 2;                        \
    const half* pK = bK + (size_t)(t) * 64 * HD;                                   \
    _Pragma("unroll")                                                              \
    for (int rep = 0; rep < 2; ++rep) {                                            \
        int idx = rep * 256 + tid;          /* 0..511 */                           \
        int row = idx >> 3, col8 = (idx & 7) * 8;                                  \
        uint32_t doff = (uint32_t)(row * AT_STRIDE + col8) * 2;                    \
        CP_ASYNC16(ob + doff,              pK + (size_t)row * HD + col8);          \
        CP_ASYNC16(ob + AT_MAT * 2 + doff, bV + (size_t)row * SEQ + (t) * 64 + col8); \
    }                                                                              \
    CP_COMMIT();                                                                   \
} while (0)

    uint32_t qf[4][4];
    {
        const half* bq = Q + ((size_t)bh * SEQ + wq) * HD;
#pragma unroll
        for (int j = 0; j < 4; ++j) {
            int e0 = 16 * j + 2 * tig;
            qf[j][0] = *(const uint32_t*)(bq + (size_t)gid * HD + e0);
            qf[j][1] = *(const uint32_t*)(bq + (size_t)(gid + 8) * HD + e0);
            qf[j][2] = *(const uint32_t*)(bq + (size_t)gid * HD + e0 + 8);
            qf[j][3] = *(const uint32_t*)(bq + (size_t)(gid + 8) * HD + e0 + 8);
        }
    }

    float cx[8][4];
#pragma unroll
    for (int nt = 0; nt < 8; ++nt)
#pragma unroll
        for (int q = 0; q < 4; ++q) cx[nt][q] = 0.f;
    float m0 = -1e30f, m1 = -1e30f, l0 = 0.f, l1 = 0.f;

    ISSUEA(0);

    for (int kt = 0; kt < NT; ++kt) {
        __syncthreads();
        if (kt + 1 < NT) { ISSUEA(kt + 1); CP_WAIT(1); }
        else             { CP_WAIT(0); }
        __syncthreads();

        const uint32_t sbase = smu + (uint32_t)(kt & 1) * ATT_SPAN * 2;
        const uint32_t uK = sbase;
        const uint32_t uV = sbase + AT_MAT * 2;

        float sacc[8][4];
#pragma unroll
        for (int nt = 0; nt < 8; ++nt)
#pragma unroll
            for (int q = 0; q < 4; ++q) sacc[nt][q] = 0.f;

#pragma unroll
        for (int j = 0; j < 4; ++j) {
            const uint32_t coff = (uint32_t)(16 * j + bCol) * 2;
#pragma unroll
            for (int P = 0; P < 4; ++P) {
                const uint32_t off = (uint32_t)((P * 16 + bRow) * AT_STRIDE) * 2 + coff;
                uint32_t k0, k1, k2, k3;
                ldm_x4(k0, k1, k2, k3, uK + off);
                mma_f16(sacc[2*P],   qf[j][0], qf[j][1], qf[j][2], qf[j][3], k0, k1);
                mma_f16(sacc[2*P+1], qf[j][0], qf[j][1], qf[j][2], qf[j][3], k2, k3);
            }
        }

        float mx0 = -1e30f, mx1 = -1e30f;
#pragma unroll
        for (int nt = 0; nt < 8; ++nt) {
            mx0 = fmaxf(mx0, fmaxf(sacc[nt][0], sacc[nt][1]));
            mx1 = fmaxf(mx1, fmaxf(sacc[nt][2], sacc[nt][3]));
        }
        mx0 = fmaxf(mx0, __shfl_xor_sync(0xffffffffu, mx0, 1));
        mx0 = fmaxf(mx0, __shfl_xor_sync(0xffffffffu, mx0, 2));
        mx1 = fmaxf(mx1, __shfl_xor_sync(0xffffffffu, mx1, 1));
        mx1 = fmaxf(mx1, __shfl_xor_sync(0xffffffffu, mx1, 2));
        float mn0 = fmaxf(m0, mx0), mn1 = fmaxf(m1, mx1);
        float r0 = __expf(m0 - mn0), r1 = __expf(m1 - mn1);
        m0 = mn0; m1 = mn1;

        float s0 = 0.f, s1 = 0.f;
#pragma unroll
        for (int nt = 0; nt < 8; ++nt) {
            float e0 = __expf(sacc[nt][0] - mn0);
            float e1 = __expf(sacc[nt][1] - mn0);
            float e2 = __expf(sacc[nt][2] - mn1);
            float e3 = __expf(sacc[nt][3] - mn1);
            sacc[nt][0] = e0; sacc[nt][1] = e1; sacc[nt][2] = e2; sacc[nt][3] = e3;
            s0 += e0 + e1; s1 += e2 + e3;
        }
        s0 += __shfl_xor_sync(0xffffffffu, s0, 1);
        s0 += __shfl_xor_sync(0xffffffffu, s0, 2);
        s1 += __shfl_xor_sync(0xffffffffu, s1, 1);
        s1 += __shfl_xor_sync(0xffffffffu, s1, 2);
        l0 = l0 * r0 + s0; l1 = l1 * r1 + s1;

#pragma unroll
        for (int nt = 0; nt < 8; ++nt) {
            cx[nt][0] *= r0; cx[nt][1] *= r0;
            cx[nt][2] *= r1; cx[nt][3] *= r1;
        }

#pragma unroll
        for (int j = 0; j < 4; ++j) {
            uint32_t pa[4];
            __half2 t0 = __floats2half2_rn(sacc[2*j][0],   sacc[2*j][1]);
            __half2 t1 = __floats2half2_rn(sacc[2*j][2],   sacc[2*j][3]);
            __half2 t2 = __floats2half2_rn(sacc[2*j+1][0], sacc[2*j+1][1]);
            __half2 t3 = __floats2half2_rn(sacc[2*j+1][2], sacc[2*j+1][3]);
            pa[0] = *(uint32_t*)&t0; pa[1] = *(uint32_t*)&t1;
            pa[2] = *(uint32_t*)&t2; pa[3] = *(uint32_t*)&t3;
            const uint32_t coff = (uint32_t)(16 * j + bCol) * 2;
#pragma unroll
            for (int P = 0; P < 4; ++P) {
                const uint32_t off = (uint32_t)((P * 16 + bRow) * AT_STRIDE) * 2 + coff;
                uint32_t v0, v1, v2, v3;
                ldm_x4(v0, v1, v2, v3, uV + off);
                mma_f16(cx[2*P],   pa[0], pa[1], pa[2], pa[3], v0, v1);
                mma_f16(cx[2*P+1], pa[0], pa[1], pa[2], pa[3], v2, v3);
            }
        }
    }
#undef ISSUEA

    // ---- epilogue: ctx fp16 single, flat [M,1024] ----
    const int b = bh >> 4, h = bh & 15;
    const float inv0 = 1.f / l0, inv1 = 1.f / l1;
    const int row0 = wq + gid, row1 = wq + gid + 8;
#pragma unroll
    for (int nt = 0; nt < 8; ++nt) {
        const int dcol = h * HD + 8 * nt + 2 * tig;
        __half2 p0 = __floats2half2_rn(cx[nt][0] * inv0, cx[nt][1] * inv0);
        __half2 p1 = __floats2half2_rn(cx[nt][2] * inv1, cx[nt][3] * inv1);
        *(uint32_t*)&ctx16[(size_t)(b * SEQ + row0) * Dh + dcol] = *(uint32_t*)&p0;
        *(uint32_t*)&ctx16[(size_t)(b * SEQ + row1) * Dh + dcol] = *(uint32_t*)&p1;
    }
}

// ---------------- launch ------------------------------------------------------
extern "C" void kernel_launch(void* const* d_in, const int* in_sizes, int n_in,
                              void* d_out, int out_size)
{
    const float* X  = (const float*)d_in[0];
    const float* Wq = (const float*)d_in[1];
    const float* bq = (const float*)d_in[2];
    const float* Wk = (const float*)d_in[3];
    const float* bk = (const float*)d_in[4];
    const float* Wv = (const float*)d_in[5];
    const float* bv = (const float*)d_in[6];
    const float* Wo = (const float*)d_in[7];
    const float* bo = (const float*)d_in[8];
    float* out = (float*)d_out;

    half *x16, *wq16, *wk16, *wv16, *wo16, *q16, *k16, *v16, *cx16;
    cudaGetSymbolAddress((void**)&x16,  g_x16);
    cudaGetSymbolAddress((void**)&wq16, g_wq16);
    cudaGetSymbolAddress((void**)&wk16, g_wk16);
    cudaGetSymbolAddress((void**)&wv16, g_wv16);
    cudaGetSymbolAddress((void**)&wo16, g_wo16);
    cudaGetSymbolAddress((void**)&q16,  g_q16);
    cudaGetSymbolAddress((void**)&k16,  g_k16);
    cudaGetSymbolAddress((void**)&v16,  g_v16);
    cudaGetSymbolAddress((void**)&cx16, g_cx16);

    cudaFuncSetAttribute(gemm_qkv, cudaFuncAttributeMaxDynamicSharedMemorySize, GEMM_SMEM);
    cudaFuncSetAttribute(gemm_out, cudaFuncAttributeMaxDynamicSharedMemorySize, GEMM_SMEM);
    cudaFuncSetAttribute(attn_mma, cudaFuncAttributeMaxDynamicSharedMemorySize, ATT_SMEM);

    dim3 thr(256);
    cvt16<<<(MROWS * Dh / 4 + 255) / 256, thr>>>(X, x16, MROWS * Dh / 4);
    {
        dim3 gw((Dh * Dh / 4 + 255) / 256, 4);
        cvtW<<<gw, thr>>>(Wq, Wk, Wv, Wo, wq16, wk16, wv16, wo16, Dh * Dh / 4);
    }

    dim3 gthr(512);
    dim3 gq(Dh / 128, MROWS / 256, 3);  // (8, 32, 3)
    gemm_qkv<<<gq, gthr, GEMM_SMEM>>>(x16, wq16, wk16, wv16, bq, bk, bv, q16, k16, v16);

    dim3 ga(SEQ / 128, BATCH * NH);     // (16, 64)
    attn_mma<<<ga, thr, ATT_SMEM>>>(q16, k16, v16, cx16);

    dim3 gg(Dh / 128, MROWS / 256);     // (8, 32)
    gemm_out<<<gg, gthr, GEMM_SMEM>>>(cx16, wo16, bo, out);
}